// round 14
// baseline (speedup 1.0000x reference)
#include <cuda_runtime.h>
#include <math.h>

#define NB   2048
#define NCTA 148
#define NTHR 256
#define TTOT (NCTA * NTHR)

typedef unsigned int       u32;
typedef unsigned long long u64;

// ---------------- static device scratch ----------------
__device__ float  g_bufM1[7356416];  // block1 f32 conv/pool outputs [n][c][lp]
__device__ short  g_bufMs[3538944];  // L2-7 i16 conv/pool outputs [n][c][lp]
__device__ u64    g_bufP[919552];    // packed activations [n][lp]
__device__ float  g_bwfc[1080];
__device__ u32    g_wp2[144];
__device__ u32    g_wp3[288];
__device__ u32    g_wp4[448];
__device__ u64    g_wp5[320];
__device__ u64    g_wp6[192];
__device__ u64    g_wp7[216];
__device__ float  g_scales[320];
__device__ double g_psd1[30720];     // block1 fp64 stat partials [8][3840]
__device__ double g_psd2[30720];
__device__ u64    g_sS1[320];        // exact int totals, layers 2-7
__device__ u64    g_sS2[320];
__device__ float  g_bna[16];
__device__ float  g_bnc[16];
__device__ int    g_tailArr;         // zero-init barrier state
__device__ int    g_tailGen;         // monotonic generation (never reset)

__device__ __forceinline__ void pdl_wait() {
    asm volatile("griddepcontrol.wait;" ::: "memory");
}
__device__ __forceinline__ int popc_w(u32 x) { return __popc(x); }
__device__ __forceinline__ int popc_w(u64 x) { return __popcll(x); }
__device__ __forceinline__ u64 pack2f(float lo, float hi) {
    u64 d; asm("mov.b64 %0,{%1,%2};" : "=l"(d) : "f"(lo), "f"(hi)); return d;
}
__device__ __forceinline__ void unpack2f(u64 v, float& lo, float& hi) {
    asm("mov.b64 {%0,%1},%2;" : "=f"(lo), "=f"(hi) : "l"(v));
}
__device__ __forceinline__ u64 ffma2(u64 a, u64 b, u64 c) {
    u64 d; asm("fma.rn.f32x2 %0,%1,%2,%3;" : "=l"(d) : "l"(a), "l"(b), "l"(c)); return d;
}

// grid barrier for the tail kernel (148 co-resident CTAs; gen is monotonic
// across graph replays so no reset is needed)
__device__ __forceinline__ void tail_sync()
{
    __syncthreads();
    if (threadIdx.x == 0) {
        __threadfence();
        int gen = *(volatile int*)&g_tailGen;
        if (atomicAdd(&g_tailArr, 1) == NCTA - 1) {
            g_tailArr = 0;
            __threadfence();
            atomicExch(&g_tailGen, gen + 1);
        } else {
            while (*(volatile int*)&g_tailGen == gen) __nanosleep(64);
            __threadfence();
        }
    }
    __syncthreads();
}

// ---------------- weight binarization L2-7+FC + zero all stat slots ----------------
__global__ void binw_all_kernel(
    const float* w2, const float* w3, const float* w4,
    const float* w5, const float* w6, const float* w7, const float* wfc)
{
    const int bx = blockIdx.x;
    const int tid = threadIdx.x;
    if (bx == 313) {
        for (int i = tid; i < 320; i += 64) { g_sS1[i] = 0; g_sS2[i] = 0; }
        return;
    }

    const int starts[8] = {0, 12, 44, 108, 172, 236, 308, 313};
    const int CINs[7]   = {8, 12, 32, 64, 64, 64, 216};
    const int Ks[7]     = {12, 9, 7, 5, 3, 3, 1};
    const int soff[7]   = {0, 12, 44, 108, 172, 236, 0};
    const float* ws[7]  = {w2, w3, w4, w5, w6, w7, wfc};

    int layer = 0;
    while (bx >= starts[layer + 1]) layer++;
    const int o   = bx - starts[layer];
    const int CIN = CINs[layer], K = Ks[layer], IK = CIN * K;
    const float* wrow = ws[layer] + o * IK;

    __shared__ double sd[64];
    double acc = 0.0;
    for (int i = tid; i < IK; i += 64) acc += (double)fabsf(wrow[i]);
    sd[tid] = acc;
    __syncthreads();
    for (int s = 32; s > 0; s >>= 1) {
        if (tid < s) sd[tid] += sd[tid + s];
        __syncthreads();
    }
    const float scale = (float)(sd[0] / (double)IK);

    if (layer == 6) {
        for (int i = tid; i < IK; i += 64) {
            float v = wrow[i];
            g_bwfc[o * IK + i] = (v > 0.f) ? scale : ((v < 0.f) ? -scale : 0.f);
        }
    } else {
        if (tid == 0) g_scales[soff[layer] + o] = scale;
        if (layer <= 2) {
            u32* wp = (layer == 0) ? g_wp2 : (layer == 1) ? g_wp3 : g_wp4;
            for (int k = tid; k < K; k += 64) {
                u32 word = 0;
                for (int ci = 0; ci < CIN; ci++)
                    if (wrow[ci * K + k] > 0.f) word |= (1u << ci);
                wp[o * K + k] = word;
            }
        } else {
            u64* wp = (layer == 3) ? g_wp5 : (layer == 4) ? g_wp6 : g_wp7;
            for (int k = tid; k < K; k += 64) {
                u64 word = 0;
                for (int ci = 0; ci < CIN; ci++)
                    if (wrow[ci * K + k] > 0.f) word |= (1ull << ci);
                wp[o * K + k] = word;
            }
        }
    }
}

// =============== block 1: warp-cooperative FFMA2 conv + pool-sharing ===============
__global__ void __launch_bounds__(256) conv1_kernel(
    const float* __restrict__ x, const float* __restrict__ w1,
    float* __restrict__ out,
    double* __restrict__ ps1, double* __restrict__ ps2)
{
    constexpr int LIN = 3600, LP = 449, CO = 8;
    __shared__ float sbw[128];
    __shared__ u64 sw2[128];
    const int tid = threadIdx.x;
    if (tid < 8) {
        const float* wr = w1 + tid * 16;
        float s = 0.f;
#pragma unroll
        for (int k = 0; k < 16; k++) s += fabsf(wr[k]);
        s *= 0.0625f;
#pragma unroll
        for (int k = 0; k < 16; k++) {
            float v = wr[k];
            sbw[tid * 16 + k] = (v > 0.f) ? s : ((v < 0.f) ? -s : 0.f);
        }
    }
    __syncthreads();
    if (tid < 128) { float w = sbw[tid]; sw2[tid] = pack2f(w, w); }
    __syncthreads();

    const int lane = tid & 31, warp = tid >> 5;
    const int gw    = blockIdx.x * 8 + warp;   // < 30720 exact
    const int n     = gw / 15;
    const int chunk = gw - n * 15;
    const int lp    = chunk * 31 + lane;
    const int p0    = lp * 4;
    const int base  = p0 * 2 - 7;
    const float* __restrict__ xp = x + (size_t)n * LIN;

    float win[22];
#pragma unroll
    for (int t = 0; t < 22; t++) {
        int p = base + t;
        win[t] = (p >= 0 && p < LIN) ? xp[p] : 0.f;
    }
    u64 pz[20];
#pragma unroll
    for (int t = 0; t < 20; t++) pz[t] = pack2f(win[t], win[t + 2]);

    const bool outv = (lane < 31) && (lp < LP);

    __shared__ float sh1[8][CO], sh2[8][CO];

#pragma unroll
    for (int c = 0; c < CO; c++) {
        u64 a0 = 0, a1 = 0;
#pragma unroll
        for (int k = 0; k < 16; k++) {
            u64 wk = sw2[c * 16 + k];
            a0 = ffma2(pz[k],     wk, a0);
            a1 = ffma2(pz[4 + k], wk, a1);
        }
        float s0, s1, s2v, s3;
        unpack2f(a0, s0, s1);
        unpack2f(a1, s2v, s3);
        float max4 = fmaxf(fmaxf(s0, s1), fmaxf(s2v, s3));
        float nb   = __shfl_down_sync(0xFFFFFFFFu, max4, 1);
        float m    = fmaxf(max4, nb);
        if (outv) out[((size_t)n * CO + c) * LP + lp] = m;

        float f1 = outv ? m : 0.f;
        float f2 = outv ? m * m : 0.f;
#pragma unroll
        for (int off = 16; off > 0; off >>= 1) {
            f1 += __shfl_down_sync(0xFFFFFFFFu, f1, off);
            f2 += __shfl_down_sync(0xFFFFFFFFu, f2, off);
        }
        if (lane == 0) { sh1[warp][c] = f1; sh2[warp][c] = f2; }
    }
    __syncthreads();
    if (tid < CO) {
        double t1 = 0.0, t2 = 0.0;
#pragma unroll
        for (int q = 0; q < 8; q++) { t1 += (double)sh1[q][tid]; t2 += (double)sh2[q][tid]; }
        ps1[tid * 3840 + blockIdx.x] = t1;
        ps2[tid * 3840 + blockIdx.x] = t2;
    }
}

// =============== block1 BN finalize ===============
__global__ void stats_fin_d(const double* __restrict__ ps1, const double* __restrict__ ps2,
                            const float* __restrict__ gamma, const float* __restrict__ beta,
                            float* __restrict__ bna, float* __restrict__ bnc)
{
    pdl_wait();
    const int ch = blockIdx.x, G = 3840;
    __shared__ double s1[256], s2[256];
    double a1 = 0.0, a2 = 0.0;
    for (int i = threadIdx.x; i < G; i += 256) { a1 += ps1[ch * G + i]; a2 += ps2[ch * G + i]; }
    s1[threadIdx.x] = a1; s2[threadIdx.x] = a2;
    __syncthreads();
    for (int s = 128; s > 0; s >>= 1) {
        if (threadIdx.x < s) { s1[threadIdx.x] += s1[threadIdx.x + s]; s2[threadIdx.x] += s2[threadIdx.x + s]; }
        __syncthreads();
    }
    if (threadIdx.x == 0) {
        const double invcnt = 1.0 / (2048.0 * 449.0);
        double m = s1[0] * invcnt;
        double v = s2[0] * invcnt - m * m;
        if (v < 0.0) v = 0.0;
        double a = (double)gamma[ch] / sqrt(v + 1e-5);
        bna[ch] = (float)a;
        bnc[ch] = (float)((double)beta[ch] - m * a);
    }
}

// =============== warp-cooperative XNOR conv+pool (L2-L4) ===============
template <int CIN, int COUT, int CB, int K, int STR, int PAD, int PK, int PS,
          int LIN, int LP, int LC, int WPI, int NT>
__global__ void __launch_bounds__(NT) conv_popc_warp(
    const u32* __restrict__ inP, short* __restrict__ out,
    const u32* __restrict__ wp,
    u64* __restrict__ sT1, u64* __restrict__ sT2)
{
    pdl_wait();
    constexpr int OPW   = (PK == 5) ? 30 : 31;
    constexpr int WREAL = (PS - 1) * STR + K;
    constexpr int IPC   = (NT / 32) / WPI;
    constexpr u32 MCIN  = (CIN >= 32) ? 0xFFFFFFFFu : ((1u << CIN) - 1u);

    __shared__ u32 sw[COUT * K];
    __shared__ int ssum[COUT], ssq[COUT];
    const int tid = threadIdx.x;
    for (int i = tid; i < COUT * K; i += NT) sw[i] = wp[i];
    if (tid < COUT) { ssum[tid] = 0; ssq[tid] = 0; }
    __syncthreads();

    const int lane = tid & 31, warp = tid >> 5;
    const int n     = blockIdx.x * IPC + warp / WPI;
    const int chunk = warp % WPI;
    const int lp    = chunk * OPW + lane;
    const int p0    = lp * PS;
    const int base  = p0 * STR - PAD;
    const u32* __restrict__ ib = inP + (size_t)n * LIN;

    u32 win[WREAL], msk[WREAL];
#pragma unroll
    for (int t = 0; t < WREAL; t++) {
        int p = base + t;
        bool v = (p >= 0 && p < LIN);
        win[t] = v ? ib[p] : 0u;
        msk[t] = v ? MCIN : 0u;
    }
    int cnt[PS];
    bool posv[PS];
#pragma unroll
    for (int d = 0; d < PS; d++) {
        posv[d] = (p0 + d) < LC;
        int cc = 0;
#pragma unroll
        for (int k = 0; k < K; k++) cc += (msk[d * STR + k] != 0) ? CIN : 0;
        cnt[d] = cc;
    }
    const bool outv = (lane < OPW) && (lp < LP);

#pragma unroll 1
    for (int cb = 0; cb < COUT; cb += CB) {
        int P[CB][PS];
#pragma unroll
        for (int c = 0; c < CB; c++)
#pragma unroll
            for (int d = 0; d < PS; d++) P[c][d] = 0;
#pragma unroll
        for (int k = 0; k < K; k++) {
#pragma unroll
            for (int c = 0; c < CB; c++) {
                u32 wk = sw[(cb + c) * K + k];
#pragma unroll
                for (int d = 0; d < PS; d++) {
                    int t = d * STR + k;
                    P[c][d] += __popc(~(win[t] ^ wk) & msk[t]);
                }
            }
        }
#pragma unroll
        for (int c = 0; c < CB; c++) {
            int s0 = posv[0] ? (2 * P[c][0] - cnt[0]) : (-(1 << 30));
            int s1 = posv[1] ? (2 * P[c][1] - cnt[1]) : (-(1 << 30));
            int pmax = (s0 > s1) ? s0 : s1;
            int pm1 = __shfl_down_sync(0xFFFFFFFFu, pmax, 1);
            int m = (pmax > pm1) ? pmax : pm1;
            if (PK == 5) {
                int s02 = __shfl_down_sync(0xFFFFFFFFu, s0, 2);
                m = (m > s02) ? m : s02;
            }
            if (outv) out[((size_t)n * COUT + cb + c) * LP + lp] = (short)m;
            int r1 = __reduce_add_sync(0xFFFFFFFFu, outv ? m : 0);
            int r2 = __reduce_add_sync(0xFFFFFFFFu, outv ? m * m : 0);
            if (lane == 0) { atomicAdd(&ssum[cb + c], r1); atomicAdd(&ssq[cb + c], r2); }
        }
    }
    __syncthreads();
    if (tid < COUT) {
        atomicAdd(&sT1[tid], (u64)(long long)ssum[tid]);
        atomicAdd(&sT2[tid], (u64)(long long)ssq[tid]);
    }
}

// =============== pack for block1 (plain launch: full join point) ===============
__global__ void __launch_bounds__(256) pack1_kernel(
    const float* __restrict__ m, const float* __restrict__ a, const float* __restrict__ c,
    u32* __restrict__ outP)
{
    constexpr int C = 8, LP = 449;
    __shared__ float sa[C], sc[C];
    if (threadIdx.x < C) { sa[threadIdx.x] = a[threadIdx.x]; sc[threadIdx.x] = c[threadIdx.x]; }
    __syncthreads();
    const int idx = blockIdx.x * 256 + threadIdx.x;
    const int n = idx / LP, lp = idx - n * LP;
    u32 word = 0;
#pragma unroll
    for (int co = 0; co < C; co++) {
        float v = fmaf(sa[co], m[((size_t)n * C + co) * LP + lp], sc[co]);
        if (v > 0.f) word |= (1u << co);
    }
    outP[(size_t)n * LP + lp] = word;
}

// =============== pack (i16 in) with in-CTA BN recompute (L2, L3 outputs) ===============
template <typename WT, int C, int LP>
__global__ void __launch_bounds__(256) pack_stats_kernel(
    const short* __restrict__ m,
    const u64* __restrict__ sS1, const u64* __restrict__ sS2,
    const float* __restrict__ scales,
    const float* __restrict__ gamma, const float* __restrict__ beta,
    double invcnt, WT* __restrict__ outP)
{
    pdl_wait();
    __shared__ float sa[C], sc[C], ss[C];
    if (threadIdx.x < C) {
        const int ch = threadIdx.x;
        double sl = (double)(long long)sS1[ch];
        double s2 = (double)(long long)sS2[ch];
        double scw = (double)scales[ch];
        double mm = scw * sl * invcnt;
        double e2 = scw * scw * s2 * invcnt;
        double v  = e2 - mm * mm;
        if (v < 0.0) v = 0.0;
        double a = (double)gamma[ch] / sqrt(v + 1e-5);
        sa[ch] = (float)a;
        sc[ch] = (float)((double)beta[ch] - mm * a);
        ss[ch] = (float)scw;
    }
    __syncthreads();
    const int idx = blockIdx.x * 256 + threadIdx.x;   // exact grid
    const int n = idx / LP, lp = idx - n * LP;
    WT word = 0;
#pragma unroll
    for (int co = 0; co < C; co++) {
        float f = ss[co] * (float)m[((size_t)n * C + co) * LP + lp];
        float v = fmaf(sa[co], f, sc[co]);
        if (v > 0.f) word |= ((WT)1 << co);
    }
    outP[(size_t)n * LP + lp] = word;
}

// ---------------- tail phase helpers (device functions) ----------------
__device__ void tail_coefs(const u64* __restrict__ s1g, const u64* __restrict__ s2g,
                           const float* __restrict__ scales, const float* __restrict__ gm,
                           const float* __restrict__ bt, double inv, int C,
                           float* sa, float* sc, float* ss)
{
    const int tid = threadIdx.x;
    if (tid < C) {
        double sl = (double)(long long)s1g[tid];
        double s2 = (double)(long long)s2g[tid];
        double scw = (double)scales[tid];
        double mm = scw * sl * inv;
        double e2 = scw * scw * s2 * inv;
        double v  = e2 - mm * mm;
        if (v < 0.0) v = 0.0;
        double a = (double)gm[tid] / sqrt(v + 1e-5);
        sa[tid] = (float)a;
        sc[tid] = (float)((double)bt[tid] - mm * a);
        ss[tid] = (float)scw;
    }
    __syncthreads();
}

// pack 64-channel i16 m -> u64 words, grid-strided (bounds warp-aligned)
template <int LP>
__device__ void tail_pack64(const short* m, u64* outP,
                            const float* sa, const float* sc, const float* ss, int gtid)
{
    for (int e = gtid; e < NB * LP; e += TTOT) {
        const int n = e / LP, lp = e - n * LP;
        const short* mb = m + (size_t)n * 64 * LP + lp;
        u64 w = 0;
#pragma unroll
        for (int c = 0; c < 64; c++) {
            float f = ss[c] * (float)mb[c * LP];
            if (fmaf(sa[c], f, sc[c]) > 0.f) w |= (1ull << c);
        }
        outP[e] = w;
    }
}

// 64-in XNOR conv + pool2/2 (stride1), i16 out, stats to smem then global
template <int COUT, int CO_T, int K, int PAD, int LIN, int LP>
__device__ void tail_conv(const u64* inP, short* out, const u64* __restrict__ wp,
                          u64* __restrict__ sS1, u64* __restrict__ sS2,
                          u64* sw, int* ssum, int* ssq, int gtid)
{
    const int tid = threadIdx.x, lane = tid & 31;
    for (int i = tid; i < COUT * K; i += NTHR) sw[i] = wp[i];
    if (tid < COUT) { ssum[tid] = 0; ssq[tid] = 0; }
    __syncthreads();

    constexpr int WREAL = K + 1;
    for (int e = gtid; e < NB * LP; e += TTOT) {        // warp-aligned bound
        const int n = e / LP, lp = e - n * LP;
        const int base0 = lp * 2 - PAD;
        const u64* ib = inP + (size_t)n * LIN;
        u64 win[WREAL], msk[WREAL];
        int cnt[2];
#pragma unroll
        for (int t = 0; t < WREAL; t++) {
            int p = base0 + t;
            bool v = (p >= 0 && p < LIN);
            win[t] = v ? ib[p] : 0ull;
            msk[t] = v ? ~0ull : 0ull;
        }
#pragma unroll
        for (int j = 0; j < 2; j++) {
            int cc = 0;
#pragma unroll
            for (int k = 0; k < K; k++) cc += (msk[j + k] != 0) ? 64 : 0;
            cnt[j] = cc;
        }
        short* orow = out + (size_t)n * COUT * LP + lp;
#pragma unroll 1
        for (int cb = 0; cb < COUT; cb += CO_T) {
            int P[CO_T][2];
#pragma unroll
            for (int c = 0; c < CO_T; c++) { P[c][0] = 0; P[c][1] = 0; }
#pragma unroll
            for (int k = 0; k < K; k++) {
#pragma unroll
                for (int c = 0; c < CO_T; c++) {
                    u64 wk = sw[(cb + c) * K + k];
                    P[c][0] += __popcll(~(win[k] ^ wk) & msk[k]);
                    P[c][1] += __popcll(~(win[k + 1] ^ wk) & msk[k + 1]);
                }
            }
#pragma unroll
            for (int c = 0; c < CO_T; c++) {
                int s0 = 2 * P[c][0] - cnt[0];
                int s1 = 2 * P[c][1] - cnt[1];
                int m = (s0 > s1) ? s0 : s1;
                orow[(cb + c) * LP] = (short)m;
                int r1 = __reduce_add_sync(0xFFFFFFFFu, m);
                int r2 = __reduce_add_sync(0xFFFFFFFFu, m * m);
                if (lane == 0) { atomicAdd(&ssum[cb + c], r1); atomicAdd(&ssq[cb + c], r2); }
            }
        }
    }
    __syncthreads();
    if (tid < COUT) {
        atomicAdd(&sS1[tid], (u64)(long long)ssum[tid]);
        atomicAdd(&sS2[tid], (u64)(long long)ssq[tid]);
    }
}

// =============== persistent tail: pack4 -> conv5 -> pack5 -> conv6 -> pack6 -> conv7 -> FC ===============
__global__ void __launch_bounds__(NTHR, 1) tail_kernel(
    short* bufMs, u64* bufP,
    const float* __restrict__ bwfc,
    u64* __restrict__ sS1, u64* __restrict__ sS2,
    const float* __restrict__ scales,
    const float* __restrict__ g4, const float* __restrict__ b4,
    const float* __restrict__ g5, const float* __restrict__ b5,
    const float* __restrict__ g6, const float* __restrict__ b6,
    const float* __restrict__ g7, const float* __restrict__ b7,
    float* __restrict__ out)
{
    pdl_wait();
    __shared__ float sa[72], sc[72], ss[72];
    __shared__ u64   sw[320];
    __shared__ int   ssum[72], ssq[72];
    const int gtid = blockIdx.x * NTHR + threadIdx.x;
    const int tid  = threadIdx.x;

    // pack4: L4 m (64ch, LP=26) -> bufP
    tail_coefs(sS1 + 44, sS2 + 44, scales + 44, g4, b4, 1.0 / (2048.0 * 26.0), 64, sa, sc, ss);
    tail_pack64<26>(bufMs, bufP, sa, sc, ss, gtid);
    tail_sync();

    // conv5: 64->64, k5 p2, LIN26 LP13
    tail_conv<64, 16, 5, 2, 26, 13>(bufP, bufMs, g_wp5, sS1 + 108, sS2 + 108, sw, ssum, ssq, gtid);
    tail_sync();

    // pack5
    tail_coefs(sS1 + 108, sS2 + 108, scales + 108, g5, b5, 1.0 / (2048.0 * 13.0), 64, sa, sc, ss);
    tail_pack64<13>(bufMs, bufP, sa, sc, ss, gtid);
    tail_sync();

    // conv6: 64->64, k3 p1, LIN13 LP6
    tail_conv<64, 16, 3, 1, 13, 6>(bufP, bufMs, g_wp6, sS1 + 172, sS2 + 172, sw, ssum, ssq, gtid);
    tail_sync();

    // pack6
    tail_coefs(sS1 + 172, sS2 + 172, scales + 172, g6, b6, 1.0 / (2048.0 * 6.0), 64, sa, sc, ss);
    tail_pack64<6>(bufMs, bufP, sa, sc, ss, gtid);
    tail_sync();

    // conv7: 64->72, k3 p1, LIN6 LP3
    tail_conv<72, 24, 3, 1, 6, 3>(bufP, bufMs, g_wp7, sS1 + 236, sS2 + 236, sw, ssum, ssq, gtid);
    tail_sync();

    // FC (+ block7 BN recompute)
    tail_coefs(sS1 + 236, sS2 + 236, scales + 236, g7, b7, 1.0 / (2048.0 * 3.0), 72, sa, sc, ss);
    (void)tid;
    for (int e = gtid; e < NB * 5; e += TTOT) {
        const int n = e / 5, j = e - n * 5;
        const short* mb = bufMs + (size_t)n * 216;    // [n][c][lp], lp=3
        const float* wb = bwfc + j * 216;
        float s = 0.f;
#pragma unroll 4
        for (int co = 0; co < 72; co++) {
            float av = sa[co], cv = sc[co], swv = ss[co];
#pragma unroll
            for (int l = 0; l < 3; l++) {
                float f = swv * (float)mb[co * 3 + l];
                float v = fmaf(av, f, cv);
                float sg = (v > 0.f) ? 1.f : ((v < 0.f) ? -1.f : 0.f);
                s = fmaf(sg, wb[co * 3 + l], s);
            }
        }
        out[e] = s;
    }
}

// ---------------- launch: 10 nodes ----------------
extern "C" void kernel_launch(void* const* d_in, const int* in_sizes, int n_in,
                              void* d_out, int out_size)
{
    const float* x = (const float*)d_in[0];
    const float* w[7]; const float* g[7]; const float* b[7];
    const bool interleaved = (in_sizes[2] == 8);
    for (int i = 0; i < 7; i++) {
        if (interleaved) {
            w[i] = (const float*)d_in[1 + 3 * i];
            g[i] = (const float*)d_in[2 + 3 * i];
            b[i] = (const float*)d_in[3 + 3 * i];
        } else {
            w[i] = (const float*)d_in[1 + i];
            g[i] = (const float*)d_in[8 + i];
            b[i] = (const float*)d_in[15 + i];
        }
    }
    const float* wfc = (const float*)d_in[22];
    float* out = (float*)d_out;

    float *bufM1, *bwfc, *scales, *bna, *bnc;
    short *bufMs;
    u64 *bufP, *sS1, *sS2;
    u32 *wp2, *wp3, *wp4;
    double *psd1, *psd2;
    cudaGetSymbolAddress((void**)&bufM1, g_bufM1);
    cudaGetSymbolAddress((void**)&bufMs, g_bufMs);
    cudaGetSymbolAddress((void**)&bufP, g_bufP);
    cudaGetSymbolAddress((void**)&bwfc, g_bwfc);
    cudaGetSymbolAddress((void**)&wp2, g_wp2);
    cudaGetSymbolAddress((void**)&wp3, g_wp3);
    cudaGetSymbolAddress((void**)&wp4, g_wp4);
    cudaGetSymbolAddress((void**)&scales, g_scales);
    cudaGetSymbolAddress((void**)&psd1, g_psd1);
    cudaGetSymbolAddress((void**)&psd2, g_psd2);
    cudaGetSymbolAddress((void**)&sS1, g_sS1);
    cudaGetSymbolAddress((void**)&sS2, g_sS2);
    cudaGetSymbolAddress((void**)&bna, g_bna);
    cudaGetSymbolAddress((void**)&bnc, g_bnc);

    u32* bufP32 = (u32*)bufP;

    cudaLaunchAttribute pdlAttr;
    pdlAttr.id = cudaLaunchAttributeProgrammaticStreamSerialization;
    pdlAttr.val.programmaticStreamSerializationAllowed = 1;
    cudaLaunchConfig_t cfg = {};
    cfg.stream = 0;
    cfg.attrs = &pdlAttr;
    cfg.numAttrs = 1;
#define PDL_LAUNCH(grid_, block_, kern_, ...) \
    do { cfg.gridDim = grid_; cfg.blockDim = block_; \
         cudaLaunchKernelEx(&cfg, kern_, __VA_ARGS__); } while (0)

    // binw (L2-7+FC) + stat-slot zeroing; conv1 overlaps it
    binw_all_kernel<<<314, 64>>>(w[1], w[2], w[3], w[4], w[5], w[6], wfc);
    PDL_LAUNCH(dim3(3840), dim3(256), conv1_kernel, x, w[0], bufM1, psd1, psd2);
    PDL_LAUNCH(dim3(8), dim3(256), stats_fin_d, psd1, psd2, g[0], b[0], bna, bnc);

    // pack1: plain launch = full join (binw + conv1 + stats complete)
    pack1_kernel<<<3592, 256>>>(bufM1, bna, bnc, bufP32);

    // block 2: 8->12, k12 s2 p5, pool 4/2, 449->111
    PDL_LAUNCH(dim3(2048), dim3(128),
               (conv_popc_warp<8, 12, 12, 12, 2, 5, 4, 2, 449, 111, 224, 4, 128>),
               (const u32*)bufP32, bufMs, (const u32*)wp2, sS1 + 0, sS2 + 0);
    PDL_LAUNCH(dim3(888), dim3(256), (pack_stats_kernel<u32, 12, 111>),
               (const short*)bufMs, (const u64*)(sS1 + 0), (const u64*)(sS2 + 0),
               (const float*)(scales + 0), g[1], b[1], 1.0 / (2048.0 * 111.0), bufP32);

    // block 3: 12->32, k9 s1 p4, pool 5/2, 111->54
    PDL_LAUNCH(dim3(1024), dim3(128),
               (conv_popc_warp<12, 32, 16, 9, 1, 4, 5, 2, 111, 54, 111, 2, 128>),
               (const u32*)bufP32, bufMs, (const u32*)wp3, sS1 + 12, sS2 + 12);
    PDL_LAUNCH(dim3(432), dim3(256), (pack_stats_kernel<u32, 32, 54>),
               (const short*)bufMs, (const u64*)(sS1 + 12), (const u64*)(sS2 + 12),
               (const float*)(scales + 12), g[2], b[2], 1.0 / (2048.0 * 54.0), bufP32);

    // block 4: 32->64, k7 s1 p3, pool 4/2, 54->26
    PDL_LAUNCH(dim3(512), dim3(128),
               (conv_popc_warp<32, 64, 16, 7, 1, 3, 4, 2, 54, 26, 54, 1, 128>),
               (const u32*)bufP32, bufMs, (const u32*)wp4, sS1 + 44, sS2 + 44);

    // persistent tail: pack4 -> conv5 -> pack5 -> conv6 -> pack6 -> conv7 -> FC
    PDL_LAUNCH(dim3(NCTA), dim3(NTHR), tail_kernel,
               bufMs, bufP, (const float*)bwfc, sS1, sS2, (const float*)scales,
               g[3], b[3], g[4], b[4], g[5], b[5], g[6], b[6], out);
#undef PDL_LAUNCH
}

// round 15
// speedup vs baseline: 1.2150x; 1.2150x over previous
#include <cuda_runtime.h>
#include <math.h>

#define NB 2048

typedef unsigned int       u32;
typedef unsigned long long u64;

// ---------------- static device scratch ----------------
__device__ float  g_bufM1[7356416];  // block1 f32 conv/pool outputs [n][c][lp]
__device__ short  g_bufMs[3538944];  // L2-7 i16 conv/pool outputs [n][c][lp]
__device__ u64    g_bufP[919552];    // packed activations [n][lp]
__device__ float  g_bwfc[1080];
__device__ u32    g_wp2[144];
__device__ u32    g_wp3[288];
__device__ u32    g_wp4[448];
__device__ u64    g_wp5[320];
__device__ u64    g_wp6[192];
__device__ u64    g_wp7[216];
__device__ float  g_scales[320];
__device__ double g_psd1[30720];     // block1 fp64 stat partials [8][3840]
__device__ double g_psd2[30720];
__device__ u64    g_sS1[320];        // exact int totals, layers 2-7
__device__ u64    g_sS2[320];
__device__ float  g_bna[16];
__device__ float  g_bnc[16];

__device__ __forceinline__ void pdl_wait() {
    asm volatile("griddepcontrol.wait;" ::: "memory");
}
__device__ __forceinline__ int popc_w(u32 x) { return __popc(x); }
__device__ __forceinline__ int popc_w(u64 x) { return __popcll(x); }
__device__ __forceinline__ u64 pack2f(float lo, float hi) {
    u64 d; asm("mov.b64 %0,{%1,%2};" : "=l"(d) : "f"(lo), "f"(hi)); return d;
}
__device__ __forceinline__ void unpack2f(u64 v, float& lo, float& hi) {
    asm("mov.b64 {%0,%1},%2;" : "=f"(lo), "=f"(hi) : "l"(v));
}
__device__ __forceinline__ u64 ffma2(u64 a, u64 b, u64 c) {
    u64 d; asm("fma.rn.f32x2 %0,%1,%2,%3;" : "=l"(d) : "l"(a), "l"(b), "l"(c)); return d;
}

// ---------------- weight binarization L2-7+FC + zero all stat slots ----------------
__global__ void binw_all_kernel(
    const float* w2, const float* w3, const float* w4,
    const float* w5, const float* w6, const float* w7, const float* wfc)
{
    const int bx = blockIdx.x;
    const int tid = threadIdx.x;
    if (bx == 313) {
        for (int i = tid; i < 320; i += 64) { g_sS1[i] = 0; g_sS2[i] = 0; }
        return;
    }

    const int starts[8] = {0, 12, 44, 108, 172, 236, 308, 313};
    const int CINs[7]   = {8, 12, 32, 64, 64, 64, 216};
    const int Ks[7]     = {12, 9, 7, 5, 3, 3, 1};
    const int soff[7]   = {0, 12, 44, 108, 172, 236, 0};
    const float* ws[7]  = {w2, w3, w4, w5, w6, w7, wfc};

    int layer = 0;
    while (bx >= starts[layer + 1]) layer++;
    const int o   = bx - starts[layer];
    const int CIN = CINs[layer], K = Ks[layer], IK = CIN * K;
    const float* wrow = ws[layer] + o * IK;

    __shared__ double sd[64];
    double acc = 0.0;
    for (int i = tid; i < IK; i += 64) acc += (double)fabsf(wrow[i]);
    sd[tid] = acc;
    __syncthreads();
    for (int s = 32; s > 0; s >>= 1) {
        if (tid < s) sd[tid] += sd[tid + s];
        __syncthreads();
    }
    const float scale = (float)(sd[0] / (double)IK);

    if (layer == 6) {
        for (int i = tid; i < IK; i += 64) {
            float v = wrow[i];
            g_bwfc[o * IK + i] = (v > 0.f) ? scale : ((v < 0.f) ? -scale : 0.f);
        }
    } else {
        if (tid == 0) g_scales[soff[layer] + o] = scale;
        if (layer <= 2) {
            u32* wp = (layer == 0) ? g_wp2 : (layer == 1) ? g_wp3 : g_wp4;
            for (int k = tid; k < K; k += 64) {
                u32 word = 0;
                for (int ci = 0; ci < CIN; ci++)
                    if (wrow[ci * K + k] > 0.f) word |= (1u << ci);
                wp[o * K + k] = word;
            }
        } else {
            u64* wp = (layer == 3) ? g_wp5 : (layer == 4) ? g_wp6 : g_wp7;
            for (int k = tid; k < K; k += 64) {
                u64 word = 0;
                for (int ci = 0; ci < CIN; ci++)
                    if (wrow[ci * K + k] > 0.f) word |= (1ull << ci);
                wp[o * K + k] = word;
            }
        }
    }
}

// =============== block 1: warp-cooperative FFMA2 conv + pool-sharing ===============
__global__ void __launch_bounds__(256) conv1_kernel(
    const float* __restrict__ x, const float* __restrict__ w1,
    float* __restrict__ out,
    double* __restrict__ ps1, double* __restrict__ ps2)
{
    constexpr int LIN = 3600, LP = 449, CO = 8;
    __shared__ float sbw[128];
    __shared__ u64 sw2[128];
    const int tid = threadIdx.x;
    if (tid < 8) {
        const float* wr = w1 + tid * 16;
        float s = 0.f;
#pragma unroll
        for (int k = 0; k < 16; k++) s += fabsf(wr[k]);
        s *= 0.0625f;
#pragma unroll
        for (int k = 0; k < 16; k++) {
            float v = wr[k];
            sbw[tid * 16 + k] = (v > 0.f) ? s : ((v < 0.f) ? -s : 0.f);
        }
    }
    __syncthreads();
    if (tid < 128) { float w = sbw[tid]; sw2[tid] = pack2f(w, w); }
    __syncthreads();

    const int lane = tid & 31, warp = tid >> 5;
    const int gw    = blockIdx.x * 8 + warp;   // < 30720 exact
    const int n     = gw / 15;
    const int chunk = gw - n * 15;
    const int lp    = chunk * 31 + lane;
    const int p0    = lp * 4;
    const int base  = p0 * 2 - 7;
    const float* __restrict__ xp = x + (size_t)n * LIN;

    float win[22];
#pragma unroll
    for (int t = 0; t < 22; t++) {
        int p = base + t;
        win[t] = (p >= 0 && p < LIN) ? xp[p] : 0.f;
    }
    u64 pz[20];
#pragma unroll
    for (int t = 0; t < 20; t++) pz[t] = pack2f(win[t], win[t + 2]);

    const bool outv = (lane < 31) && (lp < LP);

    __shared__ float sh1[8][CO], sh2[8][CO];

#pragma unroll
    for (int c = 0; c < CO; c++) {
        u64 a0 = 0, a1 = 0;
#pragma unroll
        for (int k = 0; k < 16; k++) {
            u64 wk = sw2[c * 16 + k];
            a0 = ffma2(pz[k],     wk, a0);
            a1 = ffma2(pz[4 + k], wk, a1);
        }
        float s0, s1, s2v, s3;
        unpack2f(a0, s0, s1);
        unpack2f(a1, s2v, s3);
        float max4 = fmaxf(fmaxf(s0, s1), fmaxf(s2v, s3));
        float nb   = __shfl_down_sync(0xFFFFFFFFu, max4, 1);
        float m    = fmaxf(max4, nb);
        if (outv) out[((size_t)n * CO + c) * LP + lp] = m;

        float f1 = outv ? m : 0.f;
        float f2 = outv ? m * m : 0.f;
#pragma unroll
        for (int off = 16; off > 0; off >>= 1) {
            f1 += __shfl_down_sync(0xFFFFFFFFu, f1, off);
            f2 += __shfl_down_sync(0xFFFFFFFFu, f2, off);
        }
        if (lane == 0) { sh1[warp][c] = f1; sh2[warp][c] = f2; }
    }
    __syncthreads();
    if (tid < CO) {
        double t1 = 0.0, t2 = 0.0;
#pragma unroll
        for (int q = 0; q < 8; q++) { t1 += (double)sh1[q][tid]; t2 += (double)sh2[q][tid]; }
        ps1[tid * 3840 + blockIdx.x] = t1;
        ps2[tid * 3840 + blockIdx.x] = t2;
    }
}

// =============== block1 BN finalize ===============
__global__ void stats_fin_d(const double* __restrict__ ps1, const double* __restrict__ ps2,
                            const float* __restrict__ gamma, const float* __restrict__ beta,
                            float* __restrict__ bna, float* __restrict__ bnc)
{
    pdl_wait();
    const int ch = blockIdx.x, G = 3840;
    __shared__ double s1[256], s2[256];
    double a1 = 0.0, a2 = 0.0;
    for (int i = threadIdx.x; i < G; i += 256) { a1 += ps1[ch * G + i]; a2 += ps2[ch * G + i]; }
    s1[threadIdx.x] = a1; s2[threadIdx.x] = a2;
    __syncthreads();
    for (int s = 128; s > 0; s >>= 1) {
        if (threadIdx.x < s) { s1[threadIdx.x] += s1[threadIdx.x + s]; s2[threadIdx.x] += s2[threadIdx.x + s]; }
        __syncthreads();
    }
    if (threadIdx.x == 0) {
        const double invcnt = 1.0 / (2048.0 * 449.0);
        double m = s1[0] * invcnt;
        double v = s2[0] * invcnt - m * m;
        if (v < 0.0) v = 0.0;
        double a = (double)gamma[ch] / sqrt(v + 1e-5);
        bna[ch] = (float)a;
        bnc[ch] = (float)((double)beta[ch] - m * a);
    }
}

// =============== warp-cooperative XNOR conv+pool (L2-L4, u32), i16 out [n][c][lp] ===============
// TAP4: pack 4 consecutive taps (8-bit masks) into one u32 -> 1 popc counts 4 taps.
template <bool TAP4, int CIN, int COUT, int CB, int K, int STR, int PAD, int PK, int PS,
          int LIN, int LP, int LC, int WPI, int NT>
__global__ void __launch_bounds__(NT) conv_popc_warp(
    const u32* __restrict__ inP, short* __restrict__ out,
    const u32* __restrict__ wp,
    u64* __restrict__ sT1, u64* __restrict__ sT2)
{
    pdl_wait();
    constexpr int OPW   = (PK == 5) ? 30 : 31;
    constexpr int WREAL = (PS - 1) * STR + K;
    constexpr int IPC   = (NT / 32) / WPI;
    constexpr u32 MCIN  = (CIN >= 32) ? 0xFFFFFFFFu : ((1u << CIN) - 1u);
    constexpr int G     = (K + 3) / 4;   // tap groups (TAP4 path)

    __shared__ u32 sw[COUT * K];
    __shared__ u32 swq[TAP4 ? COUT * G : 1];
    __shared__ int ssum[COUT], ssq[COUT];
    const int tid = threadIdx.x;
    for (int i = tid; i < COUT * K; i += NT) sw[i] = wp[i];
    if (tid < COUT) { ssum[tid] = 0; ssq[tid] = 0; }
    __syncthreads();
    if (TAP4) {
        for (int i = tid; i < COUT * G; i += NT) {
            const int c = i / G, gg = i - c * G;
            swq[i] = sw[c * K + 4 * gg]
                   | (sw[c * K + 4 * gg + 1] << 8)
                   | (sw[c * K + 4 * gg + 2] << 16)
                   | (sw[c * K + 4 * gg + 3] << 24);
        }
        __syncthreads();
    }

    const int lane = tid & 31, warp = tid >> 5;
    const int n     = blockIdx.x * IPC + warp / WPI;
    const int chunk = warp % WPI;
    const int lp    = chunk * OPW + lane;
    const int p0    = lp * PS;
    const int base  = p0 * STR - PAD;
    const u32* __restrict__ ib = inP + (size_t)n * LIN;

    u32 win[WREAL], msk[WREAL];
#pragma unroll
    for (int t = 0; t < WREAL; t++) {
        int p = base + t;
        bool v = (p >= 0 && p < LIN);
        win[t] = v ? ib[p] : 0u;
        msk[t] = v ? MCIN : 0u;
    }
    int cnt[PS];
    bool posv[PS];
#pragma unroll
    for (int d = 0; d < PS; d++) {
        posv[d] = (p0 + d) < LC;
        int cc = 0;
#pragma unroll
        for (int k = 0; k < K; k++) cc += (msk[d * STR + k] != 0) ? CIN : 0;
        cnt[d] = cc;
    }
    const bool outv = (lane < OPW) && (lp < LP);

    // TAP4: prepack window/mask groups per pool-slot (reused across all channels)
    u32 wq[PS][G], mq[PS][G];
    if (TAP4) {
#pragma unroll
        for (int d = 0; d < PS; d++)
#pragma unroll
            for (int gg = 0; gg < G; gg++) {
                int t0 = d * STR + 4 * gg;
                wq[d][gg] = win[t0] | (win[t0 + 1] << 8) | (win[t0 + 2] << 16) | (win[t0 + 3] << 24);
                mq[d][gg] = msk[t0] | (msk[t0 + 1] << 8) | (msk[t0 + 2] << 16) | (msk[t0 + 3] << 24);
            }
    }

#pragma unroll 1
    for (int cb = 0; cb < COUT; cb += CB) {
        int P[CB][PS];
#pragma unroll
        for (int c = 0; c < CB; c++)
#pragma unroll
            for (int d = 0; d < PS; d++) P[c][d] = 0;
        if (TAP4) {
#pragma unroll
            for (int gg = 0; gg < G; gg++) {
#pragma unroll
                for (int c = 0; c < CB; c++) {
                    u32 wk = swq[(cb + c) * G + gg];
#pragma unroll
                    for (int d = 0; d < PS; d++)
                        P[c][d] += __popc(~(wq[d][gg] ^ wk) & mq[d][gg]);
                }
            }
        } else {
#pragma unroll
            for (int k = 0; k < K; k++) {
#pragma unroll
                for (int c = 0; c < CB; c++) {
                    u32 wk = sw[(cb + c) * K + k];
#pragma unroll
                    for (int d = 0; d < PS; d++) {
                        int t = d * STR + k;
                        P[c][d] += __popc(~(win[t] ^ wk) & msk[t]);
                    }
                }
            }
        }
#pragma unroll
        for (int c = 0; c < CB; c++) {
            int s0 = posv[0] ? (2 * P[c][0] - cnt[0]) : (-(1 << 30));
            int s1 = posv[1] ? (2 * P[c][1] - cnt[1]) : (-(1 << 30));
            int pmax = (s0 > s1) ? s0 : s1;
            int pm1 = __shfl_down_sync(0xFFFFFFFFu, pmax, 1);
            int m = (pmax > pm1) ? pmax : pm1;
            if (PK == 5) {
                int s02 = __shfl_down_sync(0xFFFFFFFFu, s0, 2);
                m = (m > s02) ? m : s02;
            }
            if (outv) out[((size_t)n * COUT + cb + c) * LP + lp] = (short)m;
            int r1 = __reduce_add_sync(0xFFFFFFFFu, outv ? m : 0);
            int r2 = __reduce_add_sync(0xFFFFFFFFu, outv ? m * m : 0);
            if (lane == 0) { atomicAdd(&ssum[cb + c], r1); atomicAdd(&ssq[cb + c], r2); }
        }
    }
    __syncthreads();
    if (tid < COUT) {
        atomicAdd(&sT1[tid], (u64)(long long)ssum[tid]);
        atomicAdd(&sT2[tid], (u64)(long long)ssq[tid]);
    }
}

// =============== XNOR-popcount conv (L5-L7, u64, PK=PS), i16 out [n][c][lp] ===============
template <typename WT, int CIN, int COUT, int CO_T, int K, int STR, int PAD, int PK, int PS, int LIN, int LP>
__global__ void __launch_bounds__(256) conv_popc_kernel(
    const WT* __restrict__ inP, short* __restrict__ out,
    const WT* __restrict__ wp,
    u64* __restrict__ sS1, u64* __restrict__ sS2)
{
    pdl_wait();
    constexpr int WREAL = (PK - 1) * STR + K;
    constexpr WT  MCIN  = (CIN >= (int)(8 * sizeof(WT))) ? (WT)~(WT)0 : (WT)(((WT)1 << CIN) - 1);

    __shared__ WT sw[CO_T * K];
    __shared__ int ssum[CO_T], ssq[CO_T];
    const int cob = blockIdx.y * CO_T;
    const int tid = threadIdx.x;
    for (int i = tid; i < CO_T * K; i += 256) sw[i] = wp[cob * K + i];
    if (tid < CO_T) { ssum[tid] = 0; ssq[tid] = 0; }
    __syncthreads();

    const int idx = blockIdx.x * 256 + tid;          // exact grid
    const int n = idx / LP, lp = idx - n * LP;
    const int base0 = lp * PS * STR - PAD;
    const WT* __restrict__ ib = inP + (size_t)n * LIN;

    WT win[WREAL], msk[WREAL];
    int cnt[PK];
#pragma unroll
    for (int t = 0; t < WREAL; t++) {
        int p = base0 + t;
        bool v = (p >= 0 && p < LIN);
        win[t] = v ? ib[p] : (WT)0;
        msk[t] = v ? MCIN : (WT)0;
    }
#pragma unroll
    for (int j = 0; j < PK; j++) {
        int cc = 0;
#pragma unroll
        for (int k = 0; k < K; k++) cc += (msk[j * STR + k] != 0) ? CIN : 0;
        cnt[j] = cc;
    }

    int P[CO_T][PK];
#pragma unroll
    for (int c = 0; c < CO_T; c++)
#pragma unroll
        for (int j = 0; j < PK; j++) P[c][j] = 0;

#pragma unroll
    for (int k = 0; k < K; k++) {
#pragma unroll
        for (int c = 0; c < CO_T; c++) {
            WT wk = sw[c * K + k];
#pragma unroll
            for (int j = 0; j < PK; j++) {
                int t = j * STR + k;
                P[c][j] += popc_w((WT)(~(win[t] ^ wk) & msk[t]));
            }
        }
    }

    const int lane = tid & 31;
#pragma unroll
    for (int c = 0; c < CO_T; c++) {
        int m = 2 * P[c][0] - cnt[0];
#pragma unroll
        for (int j = 1; j < PK; j++) {
            int s = 2 * P[c][j] - cnt[j];
            m = (s > m) ? s : m;
        }
        out[((size_t)n * COUT + cob + c) * LP + lp] = (short)m;
        int r1 = __reduce_add_sync(0xFFFFFFFFu, m);
        int r2 = __reduce_add_sync(0xFFFFFFFFu, m * m);
        if (lane == 0) { atomicAdd(&ssum[c], r1); atomicAdd(&ssq[c], r2); }
    }
    __syncthreads();
    if (tid < CO_T) {
        atomicAdd(&sS1[cob + tid], (u64)(long long)ssum[tid]);
        atomicAdd(&sS2[cob + tid], (u64)(long long)ssq[tid]);
    }
}

// =============== pack for block1 (plain launch: full join point) ===============
__global__ void __launch_bounds__(256) pack1_kernel(
    const float* __restrict__ m, const float* __restrict__ a, const float* __restrict__ c,
    u32* __restrict__ outP)
{
    constexpr int C = 8, LP = 449;
    __shared__ float sa[C], sc[C];
    if (threadIdx.x < C) { sa[threadIdx.x] = a[threadIdx.x]; sc[threadIdx.x] = c[threadIdx.x]; }
    __syncthreads();
    const int idx = blockIdx.x * 256 + threadIdx.x;
    const int n = idx / LP, lp = idx - n * LP;
    u32 word = 0;
#pragma unroll
    for (int co = 0; co < C; co++) {
        float v = fmaf(sa[co], m[((size_t)n * C + co) * LP + lp], sc[co]);
        if (v > 0.f) word |= (1u << co);
    }
    outP[(size_t)n * LP + lp] = word;
}

// =============== pack (i16 in) with in-CTA BN recompute ===============
template <typename WT, int C, int LP>
__global__ void __launch_bounds__(256) pack_stats_kernel(
    const short* __restrict__ m,
    const u64* __restrict__ sS1, const u64* __restrict__ sS2,
    const float* __restrict__ scales,
    const float* __restrict__ gamma, const float* __restrict__ beta,
    double invcnt, WT* __restrict__ outP)
{
    pdl_wait();
    __shared__ float sa[C], sc[C], ss[C];
    if (threadIdx.x < C) {
        const int ch = threadIdx.x;
        double sl = (double)(long long)sS1[ch];
        double s2 = (double)(long long)sS2[ch];
        double scw = (double)scales[ch];
        double mm = scw * sl * invcnt;
        double e2 = scw * scw * s2 * invcnt;
        double v  = e2 - mm * mm;
        if (v < 0.0) v = 0.0;
        double a = (double)gamma[ch] / sqrt(v + 1e-5);
        sa[ch] = (float)a;
        sc[ch] = (float)((double)beta[ch] - mm * a);
        ss[ch] = (float)scw;
    }
    __syncthreads();
    const int idx = blockIdx.x * 256 + threadIdx.x;   // exact grid
    const int n = idx / LP, lp = idx - n * LP;
    WT word = 0;
#pragma unroll
    for (int co = 0; co < C; co++) {
        float f = ss[co] * (float)m[((size_t)n * C + co) * LP + lp];
        float v = fmaf(sa[co], f, sc[co]);
        if (v > 0.f) word |= ((WT)1 << co);
    }
    outP[(size_t)n * LP + lp] = word;
}

// =============== FC with in-CTA block7 BN recompute (i16 in, [n][c][lp]) ===============
__global__ void fc_bn_kernel(const short* __restrict__ m7, const float* __restrict__ bwfc,
                             const u64* __restrict__ sS1, const u64* __restrict__ sS2,
                             const float* __restrict__ scales,
                             const float* __restrict__ gamma, const float* __restrict__ beta,
                             float* __restrict__ out)
{
    pdl_wait();
    __shared__ float sa[72], sc[72], ss[72];
    const int tid = threadIdx.x;
    if (tid < 72) {
        const double invcnt = 1.0 / (2048.0 * 3.0);
        double sl = (double)(long long)sS1[tid];
        double s2 = (double)(long long)sS2[tid];
        double scw = (double)scales[tid];
        double mm = scw * sl * invcnt;
        double e2 = scw * scw * s2 * invcnt;
        double v  = e2 - mm * mm;
        if (v < 0.0) v = 0.0;
        double a = (double)gamma[tid] / sqrt(v + 1e-5);
        sa[tid] = (float)a;
        sc[tid] = (float)((double)beta[tid] - mm * a);
        ss[tid] = (float)scw;
    }
    __syncthreads();

    const int idx = blockIdx.x * 256 + tid;
    if (idx >= NB * 5) return;
    const int n = idx / 5, j = idx - n * 5;
    const short* __restrict__ mb = m7 + (size_t)n * 216;   // [n][c][lp], lp=3
    const float* __restrict__ wb = bwfc + j * 216;
    float s = 0.f;
#pragma unroll 4
    for (int co = 0; co < 72; co++) {
        float av = sa[co], cv = sc[co], sw = ss[co];
#pragma unroll
        for (int l = 0; l < 3; l++) {
            float f = sw * (float)mb[co * 3 + l];
            float v = fmaf(av, f, cv);
            float sg = (v > 0.f) ? 1.f : ((v < 0.f) ? -1.f : 0.f);
            s = fmaf(sg, wb[co * 3 + l], s);
        }
    }
    out[n * 5 + j] = s;
}

// ---------------- launch ----------------
extern "C" void kernel_launch(void* const* d_in, const int* in_sizes, int n_in,
                              void* d_out, int out_size)
{
    const float* x = (const float*)d_in[0];
    const float* w[7]; const float* g[7]; const float* b[7];
    const bool interleaved = (in_sizes[2] == 8);
    for (int i = 0; i < 7; i++) {
        if (interleaved) {
            w[i] = (const float*)d_in[1 + 3 * i];
            g[i] = (const float*)d_in[2 + 3 * i];
            b[i] = (const float*)d_in[3 + 3 * i];
        } else {
            w[i] = (const float*)d_in[1 + i];
            g[i] = (const float*)d_in[8 + i];
            b[i] = (const float*)d_in[15 + i];
        }
    }
    const float* wfc = (const float*)d_in[22];
    float* out = (float*)d_out;

    float *bufM1, *bwfc, *scales, *bna, *bnc;
    short *bufMs;
    u64 *bufP, *wp5, *wp6, *wp7, *sS1, *sS2;
    u32 *wp2, *wp3, *wp4;
    double *psd1, *psd2;
    cudaGetSymbolAddress((void**)&bufM1, g_bufM1);
    cudaGetSymbolAddress((void**)&bufMs, g_bufMs);
    cudaGetSymbolAddress((void**)&bufP, g_bufP);
    cudaGetSymbolAddress((void**)&bwfc, g_bwfc);
    cudaGetSymbolAddress((void**)&wp2, g_wp2);
    cudaGetSymbolAddress((void**)&wp3, g_wp3);
    cudaGetSymbolAddress((void**)&wp4, g_wp4);
    cudaGetSymbolAddress((void**)&wp5, g_wp5);
    cudaGetSymbolAddress((void**)&wp6, g_wp6);
    cudaGetSymbolAddress((void**)&wp7, g_wp7);
    cudaGetSymbolAddress((void**)&scales, g_scales);
    cudaGetSymbolAddress((void**)&psd1, g_psd1);
    cudaGetSymbolAddress((void**)&psd2, g_psd2);
    cudaGetSymbolAddress((void**)&sS1, g_sS1);
    cudaGetSymbolAddress((void**)&sS2, g_sS2);
    cudaGetSymbolAddress((void**)&bna, g_bna);
    cudaGetSymbolAddress((void**)&bnc, g_bnc);

    u32* bufP32 = (u32*)bufP;

    cudaLaunchAttribute pdlAttr;
    pdlAttr.id = cudaLaunchAttributeProgrammaticStreamSerialization;
    pdlAttr.val.programmaticStreamSerializationAllowed = 1;
    cudaLaunchConfig_t cfg = {};
    cfg.stream = 0;
    cfg.attrs = &pdlAttr;
    cfg.numAttrs = 1;
#define PDL_LAUNCH(grid_, block_, kern_, ...) \
    do { cfg.gridDim = grid_; cfg.blockDim = block_; \
         cudaLaunchKernelEx(&cfg, kern_, __VA_ARGS__); } while (0)

    // binw (L2-7+FC) + stat-slot zeroing; conv1 overlaps it
    binw_all_kernel<<<314, 64>>>(w[1], w[2], w[3], w[4], w[5], w[6], wfc);
    PDL_LAUNCH(dim3(3840), dim3(256), conv1_kernel, x, w[0], bufM1, psd1, psd2);
    PDL_LAUNCH(dim3(8), dim3(256), stats_fin_d, psd1, psd2, g[0], b[0], bna, bnc);

    // pack1: plain launch = full join (binw + conv1 + stats complete)
    pack1_kernel<<<3592, 256>>>(bufM1, bna, bnc, bufP32);

    // block 2: 8->12, k12 s2 p5, pool 4/2, 449->111  (TAP4 packed: CIN=8, K=12)
    PDL_LAUNCH(dim3(2048), dim3(128),
               (conv_popc_warp<true, 8, 12, 12, 12, 2, 5, 4, 2, 449, 111, 224, 4, 128>),
               (const u32*)bufP32, bufMs, (const u32*)wp2, sS1 + 0, sS2 + 0);
    PDL_LAUNCH(dim3(888), dim3(256), (pack_stats_kernel<u32, 12, 111>),
               (const short*)bufMs, (const u64*)(sS1 + 0), (const u64*)(sS2 + 0),
               (const float*)(scales + 0), g[1], b[1], 1.0 / (2048.0 * 111.0), bufP32);

    // block 3: 12->32, k9 s1 p4, pool 5/2, 111->54
    PDL_LAUNCH(dim3(1024), dim3(128),
               (conv_popc_warp<false, 12, 32, 16, 9, 1, 4, 5, 2, 111, 54, 111, 2, 128>),
               (const u32*)bufP32, bufMs, (const u32*)wp3, sS1 + 12, sS2 + 12);
    PDL_LAUNCH(dim3(432), dim3(256), (pack_stats_kernel<u32, 32, 54>),
               (const short*)bufMs, (const u64*)(sS1 + 12), (const u64*)(sS2 + 12),
               (const float*)(scales + 12), g[2], b[2], 1.0 / (2048.0 * 54.0), bufP32);

    // block 4: 32->64, k7 s1 p3, pool 4/2, 54->26
    PDL_LAUNCH(dim3(512), dim3(128),
               (conv_popc_warp<false, 32, 64, 16, 7, 1, 3, 4, 2, 54, 26, 54, 1, 128>),
               (const u32*)bufP32, bufMs, (const u32*)wp4, sS1 + 44, sS2 + 44);
    PDL_LAUNCH(dim3(208), dim3(256), (pack_stats_kernel<u64, 64, 26>),
               (const short*)bufMs, (const u64*)(sS1 + 44), (const u64*)(sS2 + 44),
               (const float*)(scales + 44), g[3], b[3], 1.0 / (2048.0 * 26.0), bufP);

    // block 5: 64->64, k5 s1 p2, pool 2/2, 26->13
    PDL_LAUNCH(dim3(104, 4), dim3(256),
               (conv_popc_kernel<u64, 64, 64, 16, 5, 1, 2, 2, 2, 26, 13>),
               (const u64*)bufP, bufMs, (const u64*)wp5, sS1 + 108, sS2 + 108);
    PDL_LAUNCH(dim3(104), dim3(256), (pack_stats_kernel<u64, 64, 13>),
               (const short*)bufMs, (const u64*)(sS1 + 108), (const u64*)(sS2 + 108),
               (const float*)(scales + 108), g[4], b[4], 1.0 / (2048.0 * 13.0), bufP);

    // block 6: 64->64, k3 s1 p1, pool 2/2, 13->6
    PDL_LAUNCH(dim3(48, 4), dim3(256),
               (conv_popc_kernel<u64, 64, 64, 16, 3, 1, 1, 2, 2, 13, 6>),
               (const u64*)bufP, bufMs, (const u64*)wp6, sS1 + 172, sS2 + 172);
    PDL_LAUNCH(dim3(48), dim3(256), (pack_stats_kernel<u64, 64, 6>),
               (const short*)bufMs, (const u64*)(sS1 + 172), (const u64*)(sS2 + 172),
               (const float*)(scales + 172), g[5], b[5], 1.0 / (2048.0 * 6.0), bufP);

    // block 7: 64->72, k3 s1 p1, pool 2/2, 6->3
    PDL_LAUNCH(dim3(24, 3), dim3(256),
               (conv_popc_kernel<u64, 64, 72, 24, 3, 1, 1, 2, 2, 6, 3>),
               (const u64*)bufP, bufMs, (const u64*)wp7, sS1 + 236, sS2 + 236);

    // FC
    PDL_LAUNCH(dim3((NB * 5 + 255) / 256), dim3(256), fc_bn_kernel,
               (const short*)bufMs, (const float*)bwfc,
               (const u64*)(sS1 + 236), (const u64*)(sS2 + 236),
               (const float*)(scales + 236), g[6], b[6], out);
#undef PDL_LAUNCH
}

// round 16
// speedup vs baseline: 1.2556x; 1.0334x over previous
#include <cuda_runtime.h>
#include <math.h>

#define NB 2048

typedef unsigned int       u32;
typedef unsigned long long u64;

// ---------------- static device scratch ----------------
__device__ float  g_bufM1[7356416];  // block1 f32 conv/pool outputs [n][c][lp]
__device__ short  g_bufMs[3538944];  // L2-7 i16 conv/pool outputs [n][c][lp]
__device__ u64    g_bufP[919552];    // packed activations [n][lp]
__device__ float  g_bwfc[1080];
__device__ u32    g_wp2[144];
__device__ u32    g_wp3[288];
__device__ u32    g_wp4[448];
__device__ u64    g_wp5[320];
__device__ u64    g_wp6[192];
__device__ u64    g_wp7[216];
__device__ float  g_scales[320];
__device__ double g_psd1[30720];     // block1 fp64 stat partials [8][3840]
__device__ double g_psd2[30720];
__device__ u64    g_sS1[320];        // exact int totals, layers 2-7
__device__ u64    g_sS2[320];
__device__ float  g_bna[16];
__device__ float  g_bnc[16];

__device__ __forceinline__ void pdl_wait() {
    asm volatile("griddepcontrol.wait;" ::: "memory");
}
__device__ __forceinline__ int popc_w(u32 x) { return __popc(x); }
__device__ __forceinline__ int popc_w(u64 x) { return __popcll(x); }
__device__ __forceinline__ u64 pack2f(float lo, float hi) {
    u64 d; asm("mov.b64 %0,{%1,%2};" : "=l"(d) : "f"(lo), "f"(hi)); return d;
}
__device__ __forceinline__ void unpack2f(u64 v, float& lo, float& hi) {
    asm("mov.b64 {%0,%1},%2;" : "=f"(lo), "=f"(hi) : "l"(v));
}
__device__ __forceinline__ u64 ffma2(u64 a, u64 b, u64 c) {
    u64 d; asm("fma.rn.f32x2 %0,%1,%2,%3;" : "=l"(d) : "l"(a), "l"(b), "l"(c)); return d;
}

// ---------------- weight binarization L2-7+FC + zero all stat slots ----------------
__global__ void binw_all_kernel(
    const float* w2, const float* w3, const float* w4,
    const float* w5, const float* w6, const float* w7, const float* wfc)
{
    const int bx = blockIdx.x;
    const int tid = threadIdx.x;
    if (bx == 313) {
        for (int i = tid; i < 320; i += 64) { g_sS1[i] = 0; g_sS2[i] = 0; }
        return;
    }

    const int starts[8] = {0, 12, 44, 108, 172, 236, 308, 313};
    const int CINs[7]   = {8, 12, 32, 64, 64, 64, 216};
    const int Ks[7]     = {12, 9, 7, 5, 3, 3, 1};
    const int soff[7]   = {0, 12, 44, 108, 172, 236, 0};
    const float* ws[7]  = {w2, w3, w4, w5, w6, w7, wfc};

    int layer = 0;
    while (bx >= starts[layer + 1]) layer++;
    const int o   = bx - starts[layer];
    const int CIN = CINs[layer], K = Ks[layer], IK = CIN * K;
    const float* wrow = ws[layer] + o * IK;

    __shared__ double sd[64];
    double acc = 0.0;
    for (int i = tid; i < IK; i += 64) acc += (double)fabsf(wrow[i]);
    sd[tid] = acc;
    __syncthreads();
    for (int s = 32; s > 0; s >>= 1) {
        if (tid < s) sd[tid] += sd[tid + s];
        __syncthreads();
    }
    const float scale = (float)(sd[0] / (double)IK);

    if (layer == 6) {
        for (int i = tid; i < IK; i += 64) {
            float v = wrow[i];
            g_bwfc[o * IK + i] = (v > 0.f) ? scale : ((v < 0.f) ? -scale : 0.f);
        }
    } else {
        if (tid == 0) g_scales[soff[layer] + o] = scale;
        if (layer <= 2) {
            u32* wp = (layer == 0) ? g_wp2 : (layer == 1) ? g_wp3 : g_wp4;
            for (int k = tid; k < K; k += 64) {
                u32 word = 0;
                for (int ci = 0; ci < CIN; ci++)
                    if (wrow[ci * K + k] > 0.f) word |= (1u << ci);
                wp[o * K + k] = word;
            }
        } else {
            u64* wp = (layer == 3) ? g_wp5 : (layer == 4) ? g_wp6 : g_wp7;
            for (int k = tid; k < K; k += 64) {
                u64 word = 0;
                for (int ci = 0; ci < CIN; ci++)
                    if (wrow[ci * K + k] > 0.f) word |= (1ull << ci);
                wp[o * K + k] = word;
            }
        }
    }
}

// =============== block 1: warp-cooperative FFMA2 conv + pool-sharing ===============
__global__ void __launch_bounds__(256) conv1_kernel(
    const float* __restrict__ x, const float* __restrict__ w1,
    float* __restrict__ out,
    double* __restrict__ ps1, double* __restrict__ ps2)
{
    constexpr int LIN = 3600, LP = 449, CO = 8;
    __shared__ float sbw[128];
    __shared__ u64 sw2[128];
    const int tid = threadIdx.x;
    if (tid < 8) {
        const float* wr = w1 + tid * 16;
        float s = 0.f;
#pragma unroll
        for (int k = 0; k < 16; k++) s += fabsf(wr[k]);
        s *= 0.0625f;
#pragma unroll
        for (int k = 0; k < 16; k++) {
            float v = wr[k];
            sbw[tid * 16 + k] = (v > 0.f) ? s : ((v < 0.f) ? -s : 0.f);
        }
    }
    __syncthreads();
    if (tid < 128) { float w = sbw[tid]; sw2[tid] = pack2f(w, w); }
    __syncthreads();

    const int lane = tid & 31, warp = tid >> 5;
    const int gw    = blockIdx.x * 8 + warp;   // < 30720 exact
    const int n     = gw / 15;
    const int chunk = gw - n * 15;
    const int lp    = chunk * 31 + lane;
    const int p0    = lp * 4;
    const int base  = p0 * 2 - 7;
    const float* __restrict__ xp = x + (size_t)n * LIN;

    float win[22];
#pragma unroll
    for (int t = 0; t < 22; t++) {
        int p = base + t;
        win[t] = (p >= 0 && p < LIN) ? xp[p] : 0.f;
    }
    u64 pz[20];
#pragma unroll
    for (int t = 0; t < 20; t++) pz[t] = pack2f(win[t], win[t + 2]);

    const bool outv = (lane < 31) && (lp < LP);

    __shared__ float sh1[8][CO], sh2[8][CO];

#pragma unroll
    for (int c = 0; c < CO; c++) {
        u64 a0 = 0, a1 = 0;
#pragma unroll
        for (int k = 0; k < 16; k++) {
            u64 wk = sw2[c * 16 + k];
            a0 = ffma2(pz[k],     wk, a0);
            a1 = ffma2(pz[4 + k], wk, a1);
        }
        float s0, s1, s2v, s3;
        unpack2f(a0, s0, s1);
        unpack2f(a1, s2v, s3);
        float max4 = fmaxf(fmaxf(s0, s1), fmaxf(s2v, s3));
        float nb   = __shfl_down_sync(0xFFFFFFFFu, max4, 1);
        float m    = fmaxf(max4, nb);
        if (outv) out[((size_t)n * CO + c) * LP + lp] = m;

        float f1 = outv ? m : 0.f;
        float f2 = outv ? m * m : 0.f;
#pragma unroll
        for (int off = 16; off > 0; off >>= 1) {
            f1 += __shfl_down_sync(0xFFFFFFFFu, f1, off);
            f2 += __shfl_down_sync(0xFFFFFFFFu, f2, off);
        }
        if (lane == 0) { sh1[warp][c] = f1; sh2[warp][c] = f2; }
    }
    __syncthreads();
    if (tid < CO) {
        double t1 = 0.0, t2 = 0.0;
#pragma unroll
        for (int q = 0; q < 8; q++) { t1 += (double)sh1[q][tid]; t2 += (double)sh2[q][tid]; }
        ps1[tid * 3840 + blockIdx.x] = t1;
        ps2[tid * 3840 + blockIdx.x] = t2;
    }
}

// =============== block1 BN finalize ===============
__global__ void stats_fin_d(const double* __restrict__ ps1, const double* __restrict__ ps2,
                            const float* __restrict__ gamma, const float* __restrict__ beta,
                            float* __restrict__ bna, float* __restrict__ bnc)
{
    pdl_wait();
    const int ch = blockIdx.x, G = 3840;
    __shared__ double s1[256], s2[256];
    double a1 = 0.0, a2 = 0.0;
    for (int i = threadIdx.x; i < G; i += 256) { a1 += ps1[ch * G + i]; a2 += ps2[ch * G + i]; }
    s1[threadIdx.x] = a1; s2[threadIdx.x] = a2;
    __syncthreads();
    for (int s = 128; s > 0; s >>= 1) {
        if (threadIdx.x < s) { s1[threadIdx.x] += s1[threadIdx.x + s]; s2[threadIdx.x] += s2[threadIdx.x + s]; }
        __syncthreads();
    }
    if (threadIdx.x == 0) {
        const double invcnt = 1.0 / (2048.0 * 449.0);
        double m = s1[0] * invcnt;
        double v = s2[0] * invcnt - m * m;
        if (v < 0.0) v = 0.0;
        double a = (double)gamma[ch] / sqrt(v + 1e-5);
        bna[ch] = (float)a;
        bnc[ch] = (float)((double)beta[ch] - m * a);
    }
}

// =============== warp-cooperative XNOR conv+pool (L2-L4, u32), i16 out [n][c][lp] ===============
// TPG taps packed per u32 (shift = 32/TPG); padded tap slots get zero weight+mask
// so packed popcount is bit-identical to the per-tap sum. TPG=1 -> original path.
template <int TPG, int CIN, int COUT, int CB, int K, int STR, int PAD, int PK, int PS,
          int LIN, int LP, int LC, int WPI, int NT>
__global__ void __launch_bounds__(NT) conv_popc_warp(
    const u32* __restrict__ inP, short* __restrict__ out,
    const u32* __restrict__ wp,
    u64* __restrict__ sT1, u64* __restrict__ sT2)
{
    pdl_wait();
    constexpr int OPW   = (PK == 5) ? 30 : 31;
    constexpr int WREAL = (PS - 1) * STR + K;
    constexpr int IPC   = (NT / 32) / WPI;
    constexpr u32 MCIN  = (CIN >= 32) ? 0xFFFFFFFFu : ((1u << CIN) - 1u);
    constexpr int G     = (K + TPG - 1) / TPG;
    constexpr int SHIFT = 32 / TPG;

    __shared__ u32 sw[COUT * K];
    __shared__ u32 swq[(TPG > 1) ? COUT * G : 1];
    __shared__ int ssum[COUT], ssq[COUT];
    const int tid = threadIdx.x;
    for (int i = tid; i < COUT * K; i += NT) sw[i] = wp[i];
    if (tid < COUT) { ssum[tid] = 0; ssq[tid] = 0; }
    __syncthreads();
    if (TPG > 1) {
        for (int i = tid; i < COUT * G; i += NT) {
            const int c = i / G, gg = i - c * G;
            u32 v = 0;
#pragma unroll
            for (int j = 0; j < TPG; j++) {
                int k = gg * TPG + j;
                if (k < K) v |= sw[c * K + k] << (j * SHIFT);
            }
            swq[i] = v;
        }
        __syncthreads();
    }

    const int lane = tid & 31, warp = tid >> 5;
    const int n     = blockIdx.x * IPC + warp / WPI;
    const int chunk = warp % WPI;
    const int lp    = chunk * OPW + lane;
    const int p0    = lp * PS;
    const int base  = p0 * STR - PAD;
    const u32* __restrict__ ib = inP + (size_t)n * LIN;

    u32 win[WREAL], msk[WREAL];
#pragma unroll
    for (int t = 0; t < WREAL; t++) {
        int p = base + t;
        bool v = (p >= 0 && p < LIN);
        win[t] = v ? ib[p] : 0u;
        msk[t] = v ? MCIN : 0u;
    }
    int cnt[PS];
    bool posv[PS];
#pragma unroll
    for (int d = 0; d < PS; d++) {
        posv[d] = (p0 + d) < LC;
        int cc = 0;
#pragma unroll
        for (int k = 0; k < K; k++) cc += (msk[d * STR + k] != 0) ? CIN : 0;
        cnt[d] = cc;
    }
    const bool outv = (lane < OPW) && (lp < LP);

    // packed window/mask groups per pool-slot (reused across all channels)
    u32 wq[PS][(TPG > 1) ? G : 1], mq[PS][(TPG > 1) ? G : 1];
    if (TPG > 1) {
#pragma unroll
        for (int d = 0; d < PS; d++)
#pragma unroll
            for (int gg = 0; gg < G; gg++) {
                u32 vw = 0, vm = 0;
#pragma unroll
                for (int j = 0; j < TPG; j++) {
                    int k = gg * TPG + j;
                    if (k < K) {
                        int t = d * STR + k;
                        vw |= win[t] << (j * SHIFT);
                        vm |= msk[t] << (j * SHIFT);
                    }
                }
                wq[d][gg] = vw;
                mq[d][gg] = vm;
            }
    }

#pragma unroll 1
    for (int cb = 0; cb < COUT; cb += CB) {
        int P[CB][PS];
#pragma unroll
        for (int c = 0; c < CB; c++)
#pragma unroll
            for (int d = 0; d < PS; d++) P[c][d] = 0;
        if (TPG > 1) {
#pragma unroll
            for (int gg = 0; gg < G; gg++) {
#pragma unroll
                for (int c = 0; c < CB; c++) {
                    u32 wk = swq[(cb + c) * G + gg];
#pragma unroll
                    for (int d = 0; d < PS; d++)
                        P[c][d] += __popc(~(wq[d][gg] ^ wk) & mq[d][gg]);
                }
            }
        } else {
#pragma unroll
            for (int k = 0; k < K; k++) {
#pragma unroll
                for (int c = 0; c < CB; c++) {
                    u32 wk = sw[(cb + c) * K + k];
#pragma unroll
                    for (int d = 0; d < PS; d++) {
                        int t = d * STR + k;
                        P[c][d] += __popc(~(win[t] ^ wk) & msk[t]);
                    }
                }
            }
        }
#pragma unroll
        for (int c = 0; c < CB; c++) {
            int s0 = posv[0] ? (2 * P[c][0] - cnt[0]) : (-(1 << 30));
            int s1 = posv[1] ? (2 * P[c][1] - cnt[1]) : (-(1 << 30));
            int pmax = (s0 > s1) ? s0 : s1;
            int pm1 = __shfl_down_sync(0xFFFFFFFFu, pmax, 1);
            int m = (pmax > pm1) ? pmax : pm1;
            if (PK == 5) {
                int s02 = __shfl_down_sync(0xFFFFFFFFu, s0, 2);
                m = (m > s02) ? m : s02;
            }
            if (outv) out[((size_t)n * COUT + cb + c) * LP + lp] = (short)m;
            int r1 = __reduce_add_sync(0xFFFFFFFFu, outv ? m : 0);
            int r2 = __reduce_add_sync(0xFFFFFFFFu, outv ? m * m : 0);
            if (lane == 0) { atomicAdd(&ssum[cb + c], r1); atomicAdd(&ssq[cb + c], r2); }
        }
    }
    __syncthreads();
    if (tid < COUT) {
        atomicAdd(&sT1[tid], (u64)(long long)ssum[tid]);
        atomicAdd(&sT2[tid], (u64)(long long)ssq[tid]);
    }
}

// =============== XNOR-popcount conv (L5-L7, u64, PK=PS), i16 out [n][c][lp] ===============
template <typename WT, int CIN, int COUT, int CO_T, int K, int STR, int PAD, int PK, int PS, int LIN, int LP>
__global__ void __launch_bounds__(256) conv_popc_kernel(
    const WT* __restrict__ inP, short* __restrict__ out,
    const WT* __restrict__ wp,
    u64* __restrict__ sS1, u64* __restrict__ sS2)
{
    pdl_wait();
    constexpr int WREAL = (PK - 1) * STR + K;
    constexpr WT  MCIN  = (CIN >= (int)(8 * sizeof(WT))) ? (WT)~(WT)0 : (WT)(((WT)1 << CIN) - 1);

    __shared__ WT sw[CO_T * K];
    __shared__ int ssum[CO_T], ssq[CO_T];
    const int cob = blockIdx.y * CO_T;
    const int tid = threadIdx.x;
    for (int i = tid; i < CO_T * K; i += 256) sw[i] = wp[cob * K + i];
    if (tid < CO_T) { ssum[tid] = 0; ssq[tid] = 0; }
    __syncthreads();

    const int idx = blockIdx.x * 256 + tid;          // exact grid
    const int n = idx / LP, lp = idx - n * LP;
    const int base0 = lp * PS * STR - PAD;
    const WT* __restrict__ ib = inP + (size_t)n * LIN;

    WT win[WREAL], msk[WREAL];
    int cnt[PK];
#pragma unroll
    for (int t = 0; t < WREAL; t++) {
        int p = base0 + t;
        bool v = (p >= 0 && p < LIN);
        win[t] = v ? ib[p] : (WT)0;
        msk[t] = v ? MCIN : (WT)0;
    }
#pragma unroll
    for (int j = 0; j < PK; j++) {
        int cc = 0;
#pragma unroll
        for (int k = 0; k < K; k++) cc += (msk[j * STR + k] != 0) ? CIN : 0;
        cnt[j] = cc;
    }

    int P[CO_T][PK];
#pragma unroll
    for (int c = 0; c < CO_T; c++)
#pragma unroll
        for (int j = 0; j < PK; j++) P[c][j] = 0;

#pragma unroll
    for (int k = 0; k < K; k++) {
#pragma unroll
        for (int c = 0; c < CO_T; c++) {
            WT wk = sw[c * K + k];
#pragma unroll
            for (int j = 0; j < PK; j++) {
                int t = j * STR + k;
                P[c][j] += popc_w((WT)(~(win[t] ^ wk) & msk[t]));
            }
        }
    }

    const int lane = tid & 31;
#pragma unroll
    for (int c = 0; c < CO_T; c++) {
        int m = 2 * P[c][0] - cnt[0];
#pragma unroll
        for (int j = 1; j < PK; j++) {
            int s = 2 * P[c][j] - cnt[j];
            m = (s > m) ? s : m;
        }
        out[((size_t)n * COUT + cob + c) * LP + lp] = (short)m;
        int r1 = __reduce_add_sync(0xFFFFFFFFu, m);
        int r2 = __reduce_add_sync(0xFFFFFFFFu, m * m);
        if (lane == 0) { atomicAdd(&ssum[c], r1); atomicAdd(&ssq[c], r2); }
    }
    __syncthreads();
    if (tid < CO_T) {
        atomicAdd(&sS1[cob + tid], (u64)(long long)ssum[tid]);
        atomicAdd(&sS2[cob + tid], (u64)(long long)ssq[tid]);
    }
}

// =============== pack for block1 (plain launch: full join point) ===============
__global__ void __launch_bounds__(256) pack1_kernel(
    const float* __restrict__ m, const float* __restrict__ a, const float* __restrict__ c,
    u32* __restrict__ outP)
{
    constexpr int C = 8, LP = 449;
    __shared__ float sa[C], sc[C];
    if (threadIdx.x < C) { sa[threadIdx.x] = a[threadIdx.x]; sc[threadIdx.x] = c[threadIdx.x]; }
    __syncthreads();
    const int idx = blockIdx.x * 256 + threadIdx.x;
    const int n = idx / LP, lp = idx - n * LP;
    u32 word = 0;
#pragma unroll
    for (int co = 0; co < C; co++) {
        float v = fmaf(sa[co], m[((size_t)n * C + co) * LP + lp], sc[co]);
        if (v > 0.f) word |= (1u << co);
    }
    outP[(size_t)n * LP + lp] = word;
}

// =============== pack (i16 in) with in-CTA BN recompute ===============
template <typename WT, int C, int LP>
__global__ void __launch_bounds__(256) pack_stats_kernel(
    const short* __restrict__ m,
    const u64* __restrict__ sS1, const u64* __restrict__ sS2,
    const float* __restrict__ scales,
    const float* __restrict__ gamma, const float* __restrict__ beta,
    double invcnt, WT* __restrict__ outP)
{
    pdl_wait();
    __shared__ float sa[C], sc[C], ss[C];
    if (threadIdx.x < C) {
        const int ch = threadIdx.x;
        double sl = (double)(long long)sS1[ch];
        double s2 = (double)(long long)sS2[ch];
        double scw = (double)scales[ch];
        double mm = scw * sl * invcnt;
        double e2 = scw * scw * s2 * invcnt;
        double v  = e2 - mm * mm;
        if (v < 0.0) v = 0.0;
        double a = (double)gamma[ch] / sqrt(v + 1e-5);
        sa[ch] = (float)a;
        sc[ch] = (float)((double)beta[ch] - mm * a);
        ss[ch] = (float)scw;
    }
    __syncthreads();
    const int idx = blockIdx.x * 256 + threadIdx.x;   // exact grid
    const int n = idx / LP, lp = idx - n * LP;
    WT word = 0;
#pragma unroll
    for (int co = 0; co < C; co++) {
        float f = ss[co] * (float)m[((size_t)n * C + co) * LP + lp];
        float v = fmaf(sa[co], f, sc[co]);
        if (v > 0.f) word |= ((WT)1 << co);
    }
    outP[(size_t)n * LP + lp] = word;
}

// =============== FC with in-CTA block7 BN recompute (i16 in, [n][c][lp]) ===============
__global__ void fc_bn_kernel(const short* __restrict__ m7, const float* __restrict__ bwfc,
                             const u64* __restrict__ sS1, const u64* __restrict__ sS2,
                             const float* __restrict__ scales,
                             const float* __restrict__ gamma, const float* __restrict__ beta,
                             float* __restrict__ out)
{
    pdl_wait();
    __shared__ float sa[72], sc[72], ss[72];
    const int tid = threadIdx.x;
    if (tid < 72) {
        const double invcnt = 1.0 / (2048.0 * 3.0);
        double sl = (double)(long long)sS1[tid];
        double s2 = (double)(long long)sS2[tid];
        double scw = (double)scales[tid];
        double mm = scw * sl * invcnt;
        double e2 = scw * scw * s2 * invcnt;
        double v  = e2 - mm * mm;
        if (v < 0.0) v = 0.0;
        double a = (double)gamma[tid] / sqrt(v + 1e-5);
        sa[tid] = (float)a;
        sc[tid] = (float)((double)beta[tid] - mm * a);
        ss[tid] = (float)scw;
    }
    __syncthreads();

    const int idx = blockIdx.x * 256 + tid;
    if (idx >= NB * 5) return;
    const int n = idx / 5, j = idx - n * 5;
    const short* __restrict__ mb = m7 + (size_t)n * 216;   // [n][c][lp], lp=3
    const float* __restrict__ wb = bwfc + j * 216;
    float s = 0.f;
#pragma unroll 4
    for (int co = 0; co < 72; co++) {
        float av = sa[co], cv = sc[co], sw = ss[co];
#pragma unroll
        for (int l = 0; l < 3; l++) {
            float f = sw * (float)mb[co * 3 + l];
            float v = fmaf(av, f, cv);
            float sg = (v > 0.f) ? 1.f : ((v < 0.f) ? -1.f : 0.f);
            s = fmaf(sg, wb[co * 3 + l], s);
        }
    }
    out[n * 5 + j] = s;
}

// ---------------- launch ----------------
extern "C" void kernel_launch(void* const* d_in, const int* in_sizes, int n_in,
                              void* d_out, int out_size)
{
    const float* x = (const float*)d_in[0];
    const float* w[7]; const float* g[7]; const float* b[7];
    const bool interleaved = (in_sizes[2] == 8);
    for (int i = 0; i < 7; i++) {
        if (interleaved) {
            w[i] = (const float*)d_in[1 + 3 * i];
            g[i] = (const float*)d_in[2 + 3 * i];
            b[i] = (const float*)d_in[3 + 3 * i];
        } else {
            w[i] = (const float*)d_in[1 + i];
            g[i] = (const float*)d_in[8 + i];
            b[i] = (const float*)d_in[15 + i];
        }
    }
    const float* wfc = (const float*)d_in[22];
    float* out = (float*)d_out;

    float *bufM1, *bwfc, *scales, *bna, *bnc;
    short *bufMs;
    u64 *bufP, *wp5, *wp6, *wp7, *sS1, *sS2;
    u32 *wp2, *wp3, *wp4;
    double *psd1, *psd2;
    cudaGetSymbolAddress((void**)&bufM1, g_bufM1);
    cudaGetSymbolAddress((void**)&bufMs, g_bufMs);
    cudaGetSymbolAddress((void**)&bufP, g_bufP);
    cudaGetSymbolAddress((void**)&bwfc, g_bwfc);
    cudaGetSymbolAddress((void**)&wp2, g_wp2);
    cudaGetSymbolAddress((void**)&wp3, g_wp3);
    cudaGetSymbolAddress((void**)&wp4, g_wp4);
    cudaGetSymbolAddress((void**)&wp5, g_wp5);
    cudaGetSymbolAddress((void**)&wp6, g_wp6);
    cudaGetSymbolAddress((void**)&wp7, g_wp7);
    cudaGetSymbolAddress((void**)&scales, g_scales);
    cudaGetSymbolAddress((void**)&psd1, g_psd1);
    cudaGetSymbolAddress((void**)&psd2, g_psd2);
    cudaGetSymbolAddress((void**)&sS1, g_sS1);
    cudaGetSymbolAddress((void**)&sS2, g_sS2);
    cudaGetSymbolAddress((void**)&bna, g_bna);
    cudaGetSymbolAddress((void**)&bnc, g_bnc);

    u32* bufP32 = (u32*)bufP;

    cudaLaunchAttribute pdlAttr;
    pdlAttr.id = cudaLaunchAttributeProgrammaticStreamSerialization;
    pdlAttr.val.programmaticStreamSerializationAllowed = 1;
    cudaLaunchConfig_t cfg = {};
    cfg.stream = 0;
    cfg.attrs = &pdlAttr;
    cfg.numAttrs = 1;
#define PDL_LAUNCH(grid_, block_, kern_, ...) \
    do { cfg.gridDim = grid_; cfg.blockDim = block_; \
         cudaLaunchKernelEx(&cfg, kern_, __VA_ARGS__); } while (0)

    // binw (L2-7+FC) + stat-slot zeroing; conv1 overlaps it
    binw_all_kernel<<<314, 64>>>(w[1], w[2], w[3], w[4], w[5], w[6], wfc);
    PDL_LAUNCH(dim3(3840), dim3(256), conv1_kernel, x, w[0], bufM1, psd1, psd2);
    PDL_LAUNCH(dim3(8), dim3(256), stats_fin_d, psd1, psd2, g[0], b[0], bna, bnc);

    // pack1: plain launch = full join (binw + conv1 + stats complete)
    pack1_kernel<<<3592, 256>>>(bufM1, bna, bnc, bufP32);

    // block 2: 8->12, k12 s2 p5, pool 4/2, 449->111  (TPG=4: CIN=8, 8-bit fields)
    PDL_LAUNCH(dim3(2048), dim3(128),
               (conv_popc_warp<4, 8, 12, 12, 12, 2, 5, 4, 2, 449, 111, 224, 4, 128>),
               (const u32*)bufP32, bufMs, (const u32*)wp2, sS1 + 0, sS2 + 0);
    PDL_LAUNCH(dim3(888), dim3(256), (pack_stats_kernel<u32, 12, 111>),
               (const short*)bufMs, (const u64*)(sS1 + 0), (const u64*)(sS2 + 0),
               (const float*)(scales + 0), g[1], b[1], 1.0 / (2048.0 * 111.0), bufP32);

    // block 3: 12->32, k9 s1 p4, pool 5/2, 111->54  (TPG=2: CIN=12, 16-bit fields)
    PDL_LAUNCH(dim3(1024), dim3(128),
               (conv_popc_warp<2, 12, 32, 16, 9, 1, 4, 5, 2, 111, 54, 111, 2, 128>),
               (const u32*)bufP32, bufMs, (const u32*)wp3, sS1 + 12, sS2 + 12);
    PDL_LAUNCH(dim3(432), dim3(256), (pack_stats_kernel<u32, 32, 54>),
               (const short*)bufMs, (const u64*)(sS1 + 12), (const u64*)(sS2 + 12),
               (const float*)(scales + 12), g[2], b[2], 1.0 / (2048.0 * 54.0), bufP32);

    // block 4: 32->64, k7 s1 p3, pool 4/2, 54->26  (TPG=1: CIN=32, no headroom)
    PDL_LAUNCH(dim3(512), dim3(128),
               (conv_popc_warp<1, 32, 64, 16, 7, 1, 3, 4, 2, 54, 26, 54, 1, 128>),
               (const u32*)bufP32, bufMs, (const u32*)wp4, sS1 + 44, sS2 + 44);
    PDL_LAUNCH(dim3(208), dim3(256), (pack_stats_kernel<u64, 64, 26>),
               (const short*)bufMs, (const u64*)(sS1 + 44), (const u64*)(sS2 + 44),
               (const float*)(scales + 44), g[3], b[3], 1.0 / (2048.0 * 26.0), bufP);

    // block 5: 64->64, k5 s1 p2, pool 2/2, 26->13
    PDL_LAUNCH(dim3(104, 4), dim3(256),
               (conv_popc_kernel<u64, 64, 64, 16, 5, 1, 2, 2, 2, 26, 13>),
               (const u64*)bufP, bufMs, (const u64*)wp5, sS1 + 108, sS2 + 108);
    PDL_LAUNCH(dim3(104), dim3(256), (pack_stats_kernel<u64, 64, 13>),
               (const short*)bufMs, (const u64*)(sS1 + 108), (const u64*)(sS2 + 108),
               (const float*)(scales + 108), g[4], b[4], 1.0 / (2048.0 * 13.0), bufP);

    // block 6: 64->64, k3 s1 p1, pool 2/2, 13->6
    PDL_LAUNCH(dim3(48, 4), dim3(256),
               (conv_popc_kernel<u64, 64, 64, 16, 3, 1, 1, 2, 2, 13, 6>),
               (const u64*)bufP, bufMs, (const u64*)wp6, sS1 + 172, sS2 + 172);
    PDL_LAUNCH(dim3(48), dim3(256), (pack_stats_kernel<u64, 64, 6>),
               (const short*)bufMs, (const u64*)(sS1 + 172), (const u64*)(sS2 + 172),
               (const float*)(scales + 172), g[5], b[5], 1.0 / (2048.0 * 6.0), bufP);

    // block 7: 64->72, k3 s1 p1, pool 2/2, 6->3
    PDL_LAUNCH(dim3(24, 3), dim3(256),
               (conv_popc_kernel<u64, 64, 72, 24, 3, 1, 1, 2, 2, 6, 3>),
               (const u64*)bufP, bufMs, (const u64*)wp7, sS1 + 236, sS2 + 236);

    // FC
    PDL_LAUNCH(dim3((NB * 5 + 255) / 256), dim3(256), fc_bn_kernel,
               (const short*)bufMs, (const float*)bwfc,
               (const u64*)(sS1 + 236), (const u64*)(sS2 + 236),
               (const float*)(scales + 236), g[6], b[6], out);
#undef PDL_LAUNCH
}